// round 6
// baseline (speedup 1.0000x reference)
#include <cuda_runtime.h>
#include <cuda_bf16.h>
#include <cstdint>

// TransINT scoring, single-pass quadratic form with Blackwell f32x2 FMA:
//   re = heads[rel2head[r]] * rel2mult[r]        (r = pos_r; neg_r unused)
//   s_pos = ent[ph] + re - ent[pt];  s_neg = ent[nh] + re - ent[nt]
//   A = bases[r] (2 x 256); c = ATA^{-1} (A.s)
//   exact-solution identity: ||s - A^T c||^2 = s.s - c.(A.s)
// out[0:B) = pos, out[B:2B) = neg (float32)

#define D 256
#define WARPS_PER_BLOCK 8

typedef unsigned long long ull;

__device__ __forceinline__ ull pack2(float lo, float hi) {
    ull r;
    asm("mov.b64 %0, {%1, %2};" : "=l"(r) : "f"(lo), "f"(hi));
    return r;
}
__device__ __forceinline__ void unpack2(ull v, float& lo, float& hi) {
    asm("mov.b64 {%0, %1}, %2;" : "=f"(lo), "=f"(hi) : "l"(v));
}
__device__ __forceinline__ ull ffma2(ull a, ull b, ull c) {
    ull d;
    asm("fma.rn.f32x2 %0, %1, %2, %3;" : "=l"(d) : "l"(a), "l"(b), "l"(c));
    return d;
}
__device__ __forceinline__ float pair_sum(ull v) {
    float lo, hi;
    unpack2(v, lo, hi);
    return lo + hi;
}

__global__ __launch_bounds__(WARPS_PER_BLOCK * 32, 5)
void transint_kernel(const int* __restrict__ pos_h,
                     const int* __restrict__ pos_t,
                     const int* __restrict__ pos_r,
                     const int* __restrict__ neg_h,
                     const int* __restrict__ neg_t,
                     const float* __restrict__ ent_emb,   // E x D
                     const float* __restrict__ heads,     // K x D
                     const float* __restrict__ bases,     // R x 2 x D
                     const int* __restrict__ rel2head,
                     const float* __restrict__ rel2mult,
                     float* __restrict__ out,
                     int B)
{
    const int warp = blockIdx.x * WARPS_PER_BLOCK + (threadIdx.x >> 5);
    if (warp >= B) return;
    const int lane = threadIdx.x & 31;

    // Per-sample indices (uniform across warp; broadcast loads)
    const int ph = pos_h[warp];
    const int pt = pos_t[warp];
    const int r  = pos_r[warp];
    const int nh = neg_h[warp];
    const int nt = neg_t[warp];
    const int hd = rel2head[r];
    const float mult = rel2mult[r];

    // Contiguous split: lane L owns float4 index L (dims 4L..) and L+32.
    // Each LDG.128 is a 512B contiguous warp access = 4 L1tex wavefronts.
    const int v0 = lane;
    const int v1 = lane + 32;

    const float4* __restrict__ Eph = (const float4*)(ent_emb + (size_t)ph * D);
    const float4* __restrict__ Ept = (const float4*)(ent_emb + (size_t)pt * D);
    const float4* __restrict__ Enh = (const float4*)(ent_emb + (size_t)nh * D);
    const float4* __restrict__ Ent = (const float4*)(ent_emb + (size_t)nt * D);
    const float4* __restrict__ Hd  = (const float4*)(heads   + (size_t)hd * D);
    const float4* __restrict__ A0p = (const float4*)(bases   + (size_t)r * 2 * D);
    const float4* __restrict__ A1p = (const float4*)(bases   + (size_t)r * 2 * D + D);

    // All 14 loads issued up-front (MLP covers L2/DRAM latency)
    float4 hpA = Eph[v0], hpB = Eph[v1];
    float4 tpA = Ept[v0], tpB = Ept[v1];
    float4 hnA = Enh[v0], hnB = Enh[v1];
    float4 tnA = Ent[v0], tnB = Ent[v1];
    float4 reA = Hd[v0],  reB = Hd[v1];
    float4 a0A = A0p[v0], a0B = A0p[v1];
    float4 a1A = A1p[v0], a1B = A1p[v1];

    // Repack the 8 owned floats per vector as 4 f32x2 pairs
    ull hp[4] = { pack2(hpA.x, hpA.y), pack2(hpA.z, hpA.w),
                  pack2(hpB.x, hpB.y), pack2(hpB.z, hpB.w) };
    ull tp[4] = { pack2(tpA.x, tpA.y), pack2(tpA.z, tpA.w),
                  pack2(tpB.x, tpB.y), pack2(tpB.z, tpB.w) };
    ull hn[4] = { pack2(hnA.x, hnA.y), pack2(hnA.z, hnA.w),
                  pack2(hnB.x, hnB.y), pack2(hnB.z, hnB.w) };
    ull tn[4] = { pack2(tnA.x, tnA.y), pack2(tnA.z, tnA.w),
                  pack2(tnB.x, tnB.y), pack2(tnB.z, tnB.w) };
    ull hh[4] = { pack2(reA.x, reA.y), pack2(reA.z, reA.w),
                  pack2(reB.x, reB.y), pack2(reB.z, reB.w) };
    ull A0[4] = { pack2(a0A.x, a0A.y), pack2(a0A.z, a0A.w),
                  pack2(a0B.x, a0B.y), pack2(a0B.z, a0B.w) };
    ull A1[4] = { pack2(a1A.x, a1A.y), pack2(a1A.z, a1A.w),
                  pack2(a1B.x, a1B.y), pack2(a1B.z, a1B.w) };

    const ull multp  = pack2(mult, mult);
    const ull negone = pack2(-1.0f, -1.0f);

    // 9 packed accumulators (lo accumulates even elems, hi odd)
    ull aa = 0ull, ab = 0ull, dd = 0ull;
    ull as0p = 0ull, as1p = 0ull, ssp = 0ull;
    ull as0n = 0ull, as1n = 0ull, ssn = 0ull;

    #pragma unroll
    for (int j = 0; j < 4; j++) {
        const ull sv = ffma2(tp[j], negone, ffma2(hh[j], multp, hp[j]));
        const ull nv = ffma2(tn[j], negone, ffma2(hh[j], multp, hn[j]));
        aa   = ffma2(A0[j], A0[j], aa);
        ab   = ffma2(A0[j], A1[j], ab);
        dd   = ffma2(A1[j], A1[j], dd);
        as0p = ffma2(A0[j], sv, as0p);
        as1p = ffma2(A1[j], sv, as1p);
        ssp  = ffma2(sv, sv, ssp);
        as0n = ffma2(A0[j], nv, as0n);
        as1n = ffma2(A1[j], nv, as1n);
        ssn  = ffma2(nv, nv, ssn);
    }

    // Collapse packed pairs to 9 scalars
    float r_aa   = pair_sum(aa);
    float r_ab   = pair_sum(ab);
    float r_dd   = pair_sum(dd);
    float r_as0p = pair_sum(as0p);
    float r_as1p = pair_sum(as1p);
    float r_ssp  = pair_sum(ssp);
    float r_as0n = pair_sum(as0n);
    float r_as1n = pair_sum(as1n);
    float r_ssn  = pair_sum(ssn);

    // Fused butterfly allreduce of 9 scalars
    #pragma unroll
    for (int m = 16; m > 0; m >>= 1) {
        r_aa   += __shfl_xor_sync(0xffffffffu, r_aa,   m);
        r_ab   += __shfl_xor_sync(0xffffffffu, r_ab,   m);
        r_dd   += __shfl_xor_sync(0xffffffffu, r_dd,   m);
        r_as0p += __shfl_xor_sync(0xffffffffu, r_as0p, m);
        r_as1p += __shfl_xor_sync(0xffffffffu, r_as1p, m);
        r_ssp  += __shfl_xor_sync(0xffffffffu, r_ssp,  m);
        r_as0n += __shfl_xor_sync(0xffffffffu, r_as0n, m);
        r_as1n += __shfl_xor_sync(0xffffffffu, r_as1n, m);
        r_ssn  += __shfl_xor_sync(0xffffffffu, r_ssn,  m);
    }

    if (lane == 0) {
        const float det = r_aa * r_dd - r_ab * r_ab;
        float scp, scn;
        if (det != 0.0f) {
            // exact normal-equation solve -> ||proj||^2 = ss - c . As
            const float inv_det = 1.0f / det;
            const float c0p = ( r_dd * r_as0p - r_ab * r_as1p) * inv_det;
            const float c1p = (-r_ab * r_as0p + r_aa * r_as1p) * inv_det;
            const float c0n = ( r_dd * r_as0n - r_ab * r_as1n) * inv_det;
            const float c1n = (-r_ab * r_as0n + r_aa * r_as1n) * inv_det;
            scp = r_ssp - c0p * r_as0p - c1p * r_as1p;
            scn = r_ssn - c0n * r_as0n - c1n * r_as1n;
        } else {
            // fallback c = As / aa is NOT the exact solution -> full quadratic
            const float inv_a = 1.0f / r_aa;
            const float c0p = r_as0p * inv_a, c1p = r_as1p * inv_a;
            const float c0n = r_as0n * inv_a, c1n = r_as1n * inv_a;
            scp = r_ssp - 2.0f * (c0p * r_as0p + c1p * r_as1p)
                + c0p * c0p * r_aa + 2.0f * c0p * c1p * r_ab + c1p * c1p * r_dd;
            scn = r_ssn - 2.0f * (c0n * r_as0n + c1n * r_as1n)
                + c0n * c0n * r_aa + 2.0f * c0n * c1n * r_ab + c1n * c1n * r_dd;
        }
        out[warp]     = scp;
        out[B + warp] = scn;
    }
}

extern "C" void kernel_launch(void* const* d_in, const int* in_sizes, int n_in,
                              void* d_out, int out_size) {
    const int*   pos_h    = (const int*)  d_in[0];
    const int*   pos_t    = (const int*)  d_in[1];
    const int*   pos_r    = (const int*)  d_in[2];
    const int*   neg_h    = (const int*)  d_in[3];
    const int*   neg_t    = (const int*)  d_in[4];
    // d_in[5] = neg_r (unused by the reference)
    const float* ent_emb  = (const float*)d_in[6];
    const float* heads    = (const float*)d_in[7];
    const float* bases    = (const float*)d_in[8];
    const int*   rel2head = (const int*)  d_in[9];
    const float* rel2mult = (const float*)d_in[10];
    float* out = (float*)d_out;

    const int B = in_sizes[0];
    const int blocks = (B + WARPS_PER_BLOCK - 1) / WARPS_PER_BLOCK;
    transint_kernel<<<blocks, WARPS_PER_BLOCK * 32>>>(
        pos_h, pos_t, pos_r, neg_h, neg_t,
        ent_emb, heads, bases, rel2head, rel2mult, out, B);
}